// round 4
// baseline (speedup 1.0000x reference)
#include <cuda_runtime.h>

#define NB 16
#define NC 64
#define NO 64
#define IM 32
#define LOCS 1024           // 32*32 output locations
#define KVOL 576            // 64 channels * 3 * 3
#define XS_STRIDE 18        // padded row stride (floats): (k*18)%32 distinct over
                            // 16-lane phase -> conflict-free LDS.64

typedef unsigned long long u64;

// Scratch (no allocations allowed): transposed x, and BN affine params.
__device__ float g_xT[NC * IM * IM * NB];   // layout (c, h, w, b), 4 MB
__device__ float g_scale[NO];
__device__ float g_shift[NO];

__device__ __forceinline__ u64 splat2(float w) {
    u64 d;
    asm("mov.b64 %0, {%1, %1};" : "=l"(d) : "f"(w));
    return d;
}
__device__ __forceinline__ void fma2(u64& acc, u64 a, u64 b) {
    asm("fma.rn.f32x2 %0, %1, %2, %0;" : "+l"(acc) : "l"(a), "l"(b));
}
__device__ __forceinline__ u64 add2(u64 a, u64 b) {
    u64 d;
    asm("add.rn.f32x2 %0, %1, %2;" : "=l"(d) : "l"(a), "l"(b));
    return d;
}

// ---------------------------------------------------------------------------
// x (b,c,h,w) -> xT (c,h,w,b): makes per-location patch loads coalesced.
// ---------------------------------------------------------------------------
__global__ __launch_bounds__(256) void transpose_kernel(const float* __restrict__ x) {
    int idx = blockIdx.x * 256 + threadIdx.x;      // over (c,h,w,b), b fastest
    int b = idx & 15;
    int w = (idx >> 4) & 31;
    int h = (idx >> 9) & 31;
    int c = idx >> 14;
    g_xT[idx] = x[(((b << 6) + c) << 10) + (h << 5) + w];
}

// Packed butterfly fold over 64-bit (f32x2) accumulators. After masks
// 16,8,4,2,1 lane L holds packed item L = scalars (2L, 2L+1).
template <int M, int H>
__device__ __forceinline__ void fold2(u64* acc, int lane) {
    bool up = (lane & M) != 0;
#pragma unroll
    for (int j = 0; j < H; j++) {
        u64 send = up ? acc[j] : acc[j + H];
        u64 recv = __shfl_xor_sync(0xffffffffu, send, M);
        u64 keep = up ? acc[j + H] : acc[j];
        acc[j] = add2(keep, recv);
    }
}

// ---------------------------------------------------------------------------
// Locally-connected conv. Grid: (1024 locations, 2 o-halves). Block: 256 thr.
// Each warp computes 4 output channels x 16 batches (8 packed pairs) for one
// location. Weight layout: (o, i, j, c, p, q) -> contiguous 576 per (o, loc).
// ---------------------------------------------------------------------------
__global__ __launch_bounds__(256, 2) void conv_kernel(const float* __restrict__ wgt,
                                                      const float* __restrict__ bias,
                                                      float* __restrict__ y) {
    __shared__ float xs[KVOL * XS_STRIDE];          // 41472 B
    int loc = blockIdx.x;
    int i = loc >> 5, j = loc & 31;
    int tid = threadIdx.x;

    // Stage the 3x3 patch (all 64 channels, 16 batches) as u64 pairs.
    for (int t = tid; t < KVOL * 8; t += 256) {
        int k = t >> 3, q = t & 7;                  // k = c*9+p*3+q3, q = b-pair
        int c = k / 9;
        int r = k - c * 9;
        int p = r / 3, qq = r - p * 3;
        int ih = i + p - 1, iw = j + qq - 1;
        u64 v = 0ull;
        if ((unsigned)ih < 32u && (unsigned)iw < 32u)
            v = *(const u64*)&g_xT[(((((c << 5) + ih) << 5) + iw) << 4) + (q << 1)];
        *(u64*)&xs[k * XS_STRIDE + (q << 1)] = v;
    }
    __syncthreads();

    int warp = tid >> 5, lane = tid & 31;
    int o0 = (blockIdx.y << 5) + (warp << 2);       // this warp's 4 channels

    u64 acc[32];                                     // acc[oo*8 + jb] = (b=2jb, 2jb+1)
#pragma unroll
    for (int t = 0; t < 32; t++) acc[t] = 0ull;

    const float* wb = wgt + (size_t)(o0 * LOCS + loc) * KVOL + lane;

    // Distance-4 weight prefetch: 16 scalar LDGs in flight per lane.
    float wreg[4][4];
#pragma unroll
    for (int d = 0; d < 4; d++)
#pragma unroll
        for (int oo = 0; oo < 4; oo++)
            wreg[d][oo] = wb[(size_t)oo * (LOCS * KVOL) + d * 32];

#pragma unroll
    for (int u = 0; u < 18; u++) {                   // 576 / 32 lanes
        float wv[4];
#pragma unroll
        for (int oo = 0; oo < 4; oo++) wv[oo] = wreg[u & 3][oo];
        if (u < 14) {
#pragma unroll
            for (int oo = 0; oo < 4; oo++)
                wreg[u & 3][oo] = wb[(size_t)oo * (LOCS * KVOL) + (u + 4) * 32];
        }

        const u64* xr = (const u64*)&xs[(lane + u * 32) * XS_STRIDE];
        u64 xv[8];
#pragma unroll
        for (int q = 0; q < 8; q++) xv[q] = xr[q];   // 16 floats as 8 f32x2

#pragma unroll
        for (int oo = 0; oo < 4; oo++) {
            u64 ws = splat2(wv[oo]);
#pragma unroll
            for (int jb = 0; jb < 8; jb++)
                fma2(acc[(oo << 3) + jb], ws, xv[jb]);
        }
    }

    fold2<16, 16>(acc, lane);
    fold2<8, 8>(acc, lane);
    fold2<4, 4>(acc, lane);
    fold2<2, 2>(acc, lane);
    fold2<1, 1>(acc, lane);

    // Lane L holds scalars flat=2L, 2L+1 where flat = oo*16 + b.
    float lo = __uint_as_float((unsigned)(acc[0] & 0xffffffffull));
    float hi = __uint_as_float((unsigned)(acc[0] >> 32));
#pragma unroll
    for (int s = 0; s < 2; s++) {
        int flat = (lane << 1) + s;
        int oo = flat >> 4, b = flat & 15;
        int o = o0 + oo;
        float val = (s ? hi : lo) + bias[(o << 10) + loc];
        y[(((b << 6) + o) << 10) + loc] = val;
    }
}

// ---------------------------------------------------------------------------
// BN statistics: one block per channel; reduce 16*1024 values -> scale/shift.
// ---------------------------------------------------------------------------
__global__ __launch_bounds__(256) void stats_kernel(const float* __restrict__ y,
                                                    const float* __restrict__ gamma,
                                                    const float* __restrict__ beta) {
    int o = blockIdx.x;
    float s = 0.f, s2 = 0.f;
    for (int t = threadIdx.x; t < NB * LOCS; t += 256) {
        float v = y[((((t >> 10) << 6) + o) << 10) + (t & 1023)];
        s += v;
        s2 = fmaf(v, v, s2);
    }
#pragma unroll
    for (int m = 16; m; m >>= 1) {
        s  += __shfl_xor_sync(0xffffffffu, s, m);
        s2 += __shfl_xor_sync(0xffffffffu, s2, m);
    }
    __shared__ float ss[8], ssq[8];
    int warp = threadIdx.x >> 5;
    if ((threadIdx.x & 31) == 0) { ss[warp] = s; ssq[warp] = s2; }
    __syncthreads();
    if (threadIdx.x == 0) {
        float S = 0.f, S2 = 0.f;
#pragma unroll
        for (int k = 0; k < 8; k++) { S += ss[k]; S2 += ssq[k]; }
        const float inv = 1.f / (float)(NB * LOCS);
        float mean = S * inv;
        float var = S2 * inv - mean * mean;          // biased variance (ddof=0)
        float sc = gamma[o] * rsqrtf(var + 1e-5f);
        g_scale[o] = sc;
        g_shift[o] = beta[o] - mean * sc;
    }
}

// ---------------------------------------------------------------------------
// Normalize + ReLU in place (float4 vectorized).
// ---------------------------------------------------------------------------
__global__ __launch_bounds__(256) void finalize_kernel(float* __restrict__ y) {
    int idx = blockIdx.x * 256 + threadIdx.x;        // float4 index
    int o = (idx >> 8) & 63;                         // (idx*4 / 1024) % 64
    float sc = g_scale[o], sh = g_shift[o];
    float4 v = ((float4*)y)[idx];
    v.x = fmaxf(fmaf(v.x, sc, sh), 0.f);
    v.y = fmaxf(fmaf(v.y, sc, sh), 0.f);
    v.z = fmaxf(fmaf(v.z, sc, sh), 0.f);
    v.w = fmaxf(fmaf(v.w, sc, sh), 0.f);
    ((float4*)y)[idx] = v;
}

extern "C" void kernel_launch(void* const* d_in, const int* in_sizes, int n_in,
                              void* d_out, int out_size) {
    const float* x     = (const float*)d_in[0];
    const float* w     = (const float*)d_in[1];
    const float* bias  = (const float*)d_in[2];
    const float* gamma = (const float*)d_in[3];
    const float* beta  = (const float*)d_in[4];
    float* out = (float*)d_out;

    transpose_kernel<<<4096, 256>>>(x);
    conv_kernel<<<dim3(1024, 2), 256>>>(w, bias, out);   // writes pre-BN y into out
    stats_kernel<<<64, 256>>>(out, gamma, beta);
    finalize_kernel<<<1024, 256>>>(out);                  // in-place BN + ReLU
}

// round 5
// speedup vs baseline: 1.2072x; 1.2072x over previous
#include <cuda_runtime.h>

#define NB 16
#define NO 64
#define LOCS 1024           // 32*32 output locations
#define KVOL 576            // 64 channels * 3 * 3
#define XS_STRIDE 20        // conflict-free for LDS.128 (8-lane phases)
#define WSTAGES 4           // cp.async pipeline depth

typedef unsigned long long u64;

// Scratch (no allocations allowed).
__device__ float g_xT[64 * 32 * 32 * NB];   // (c,h,w,b), 4 MB
__device__ float g_sum[NO], g_sum2[NO];
__device__ float g_scale[NO], g_shift[NO];

__device__ __forceinline__ u64 splat2(float w) {
    u64 d;
    asm("mov.b64 %0, {%1, %1};" : "=l"(d) : "f"(w));
    return d;
}
__device__ __forceinline__ void fma2(u64& acc, u64 a, u64 b) {
    asm("fma.rn.f32x2 %0, %1, %2, %0;" : "+l"(acc) : "l"(a), "l"(b));
}
__device__ __forceinline__ u64 add2(u64 a, u64 b) {
    u64 d;
    asm("add.rn.f32x2 %0, %1, %2;" : "=l"(d) : "l"(a), "l"(b));
    return d;
}
__device__ __forceinline__ void cp16(float* dst_smem, const float* src) {
    unsigned d = (unsigned)__cvta_generic_to_shared(dst_smem);
    asm volatile("cp.async.ca.shared.global [%0], [%1], 16;" :: "r"(d), "l"(src));
}
#define CP_COMMIT() asm volatile("cp.async.commit_group;")
#define CP_WAIT3()  asm volatile("cp.async.wait_group 3;")

// ---------------------------------------------------------------------------
// x (b,c,h,w) -> xT (c,h,w,b); block 0 also zeros the BN accumulators.
// ---------------------------------------------------------------------------
__global__ __launch_bounds__(256) void transpose_kernel(const float* __restrict__ x) {
    if (blockIdx.x == 0 && threadIdx.x < NO) {
        g_sum[threadIdx.x] = 0.f;
        g_sum2[threadIdx.x] = 0.f;
    }
    int idx = blockIdx.x * 256 + threadIdx.x;      // over (c,h,w,b), b fastest
    int b = idx & 15;
    int w = (idx >> 4) & 31;
    int h = (idx >> 9) & 31;
    int c = idx >> 14;
    g_xT[idx] = x[(((b << 6) + c) << 10) + (h << 5) + w];
}

// Packed butterfly fold (f32x2). After masks 16,8,4,2,1 lane L holds packed
// item L = scalars (2L, 2L+1).
template <int M, int H>
__device__ __forceinline__ void fold2(u64* acc, int lane) {
    bool up = (lane & M) != 0;
#pragma unroll
    for (int j = 0; j < H; j++) {
        u64 send = up ? acc[j] : acc[j + H];
        u64 recv = __shfl_xor_sync(0xffffffffu, send, M);
        u64 keep = up ? acc[j + H] : acc[j];
        acc[j] = add2(keep, recv);
    }
}

// ---------------------------------------------------------------------------
// Locally-connected conv + fused BN partial sums.
// Grid (1024 locs, 2 o-halves), 256 threads. Warp w: channels o0..o0+3, all
// 16 batches. Weights stream through a 4-stage cp.async smem pipeline; each
// warp's threads stage exactly the rows that warp consumes (warp-private).
// Dynamic smem: xs[576*20] | wbuf[4][32*32].
// ---------------------------------------------------------------------------
__global__ __launch_bounds__(256, 2) void conv_kernel(const float* __restrict__ wgt,
                                                      const float* __restrict__ bias,
                                                      float* __restrict__ y) {
    extern __shared__ float smem[];
    float* xs = smem;                       // 46080 B
    float* wbuf = smem + KVOL * XS_STRIDE;  // 4 * 4096 B

    int loc = blockIdx.x;
    int i = loc >> 5, j = loc & 31;
    int tid = threadIdx.x;
    int warp = tid >> 5, lane = tid & 31;

    // Weight staging map: thread t stages row o_local = t/8 (0..31), quad k4 =
    // t%8. Warp w's threads (o_local = 4w + lane/8) stage rows 4w..4w+3 — the
    // exact rows warp w consumes, so the pipeline is warp-private.
    int o_local = tid >> 3, k4 = tid & 7;
    const float* wsrc = wgt + (size_t)(((blockIdx.y << 5) + o_local) * LOCS + loc) * KVOL
                      + (k4 << 2);
#pragma unroll
    for (int s = 0; s < WSTAGES; s++) {
        cp16(&wbuf[(s << 10) + (o_local << 5) + (k4 << 2)], wsrc + s * 32);
        CP_COMMIT();
    }

    // Stage the 3x3 input patch (64 channels x 16 batches), zero padded.
    for (int t = tid; t < KVOL * 4; t += 256) {
        int k = t >> 2, bc = t & 3;
        int c = k / 9;
        int r = k - c * 9;
        int p = r / 3, q = r - p * 3;
        int ih = i + p - 1, iw = j + q - 1;
        float4 v = make_float4(0.f, 0.f, 0.f, 0.f);
        if ((unsigned)ih < 32u && (unsigned)iw < 32u)
            v = *(const float4*)&g_xT[(((((c << 5) + ih) << 5) + iw) << 4) + (bc << 2)];
        *(float4*)&xs[k * XS_STRIDE + (bc << 2)] = v;
    }
    __syncthreads();

    u64 acc[32];                             // acc[oo*8 + jb] = batches (2jb, 2jb+1)
#pragma unroll
    for (int t = 0; t < 32; t++) acc[t] = 0ull;

#pragma unroll
    for (int u = 0; u < 18; u++) {
        CP_WAIT3();
        __syncwarp();

        float wv[4];
#pragma unroll
        for (int oo = 0; oo < 4; oo++)
            wv[oo] = wbuf[((u & 3) << 10) + (((warp << 2) + oo) << 5) + lane];

        const u64* xr = (const u64*)&xs[(lane + u * 32) * XS_STRIDE];
        u64 xv[8];
#pragma unroll
        for (int q = 0; q < 8; q++) xv[q] = xr[q];

#pragma unroll
        for (int oo = 0; oo < 4; oo++) {
            u64 ws = splat2(wv[oo]);
#pragma unroll
            for (int jb = 0; jb < 8; jb++)
                fma2(acc[(oo << 3) + jb], ws, xv[jb]);
        }

        if (u < 18 - WSTAGES)
            cp16(&wbuf[(((u + WSTAGES) & 3) << 10) + (o_local << 5) + (k4 << 2)],
                 wsrc + (u + WSTAGES) * 32);
        CP_COMMIT();                          // empty groups in the tail keep
    }                                         // wait_group 3 semantics uniform

    fold2<16, 16>(acc, lane);
    fold2<8, 8>(acc, lane);
    fold2<4, 4>(acc, lane);
    fold2<2, 2>(acc, lane);
    fold2<1, 1>(acc, lane);

    // Lane L holds scalars flat = 2L, 2L+1 (flat = oo*16 + b; pairs never
    // cross an oo boundary).
    int o0 = (blockIdx.y << 5) + (warp << 2);
    int oo = lane >> 3;                       // = flat>>4 for both halves
    int o = o0 + oo;
    float bval = bias[(o << 10) + loc];
    float v0 = __uint_as_float((unsigned)(acc[0] & 0xffffffffull)) + bval;
    float v1 = __uint_as_float((unsigned)(acc[0] >> 32)) + bval;
    {
        int b0 = (lane << 1) & 15;
        y[(((b0 << 6) + o) << 10) + loc] = v0;
        y[((((b0 + 1) << 6) + o) << 10) + loc] = v1;
    }

    // Fused BN partials: reduce over the 8 lanes sharing this oo, then atomic.
    float s = v0 + v1;
    float s2 = fmaf(v0, v0, v1 * v1);
#pragma unroll
    for (int m = 4; m; m >>= 1) {
        s  += __shfl_down_sync(0xffffffffu, s, m, 8);
        s2 += __shfl_down_sync(0xffffffffu, s2, m, 8);
    }
    if ((lane & 7) == 0) {
        atomicAdd(&g_sum[o], s);
        atomicAdd(&g_sum2[o], s2);
    }
}

// ---------------------------------------------------------------------------
// Tiny param kernel: scale/shift per channel from the fused sums.
// ---------------------------------------------------------------------------
__global__ void params_kernel(const float* __restrict__ gamma,
                              const float* __restrict__ beta) {
    int o = threadIdx.x;
    const float inv = 1.f / (float)(NB * LOCS);
    float mean = g_sum[o] * inv;
    float var = g_sum2[o] * inv - mean * mean;   // biased variance (ddof=0)
    float sc = gamma[o] * rsqrtf(var + 1e-5f);
    g_scale[o] = sc;
    g_shift[o] = beta[o] - mean * sc;
}

// ---------------------------------------------------------------------------
// Normalize + ReLU in place (float4 vectorized).
// ---------------------------------------------------------------------------
__global__ __launch_bounds__(256) void finalize_kernel(float* __restrict__ y) {
    int idx = blockIdx.x * 256 + threadIdx.x;
    int o = (idx >> 8) & 63;
    float sc = g_scale[o], sh = g_shift[o];
    float4 v = ((float4*)y)[idx];
    v.x = fmaxf(fmaf(v.x, sc, sh), 0.f);
    v.y = fmaxf(fmaf(v.y, sc, sh), 0.f);
    v.z = fmaxf(fmaf(v.z, sc, sh), 0.f);
    v.w = fmaxf(fmaf(v.w, sc, sh), 0.f);
    ((float4*)y)[idx] = v;
}

extern "C" void kernel_launch(void* const* d_in, const int* in_sizes, int n_in,
                              void* d_out, int out_size) {
    const float* x     = (const float*)d_in[0];
    const float* w     = (const float*)d_in[1];
    const float* bias  = (const float*)d_in[2];
    const float* gamma = (const float*)d_in[3];
    const float* beta  = (const float*)d_in[4];
    float* out = (float*)d_out;

    const int smem_bytes = (KVOL * XS_STRIDE + WSTAGES * 32 * 32) * 4;  // 62464
    cudaFuncSetAttribute(conv_kernel, cudaFuncAttributeMaxDynamicSharedMemorySize,
                         smem_bytes);

    transpose_kernel<<<4096, 256>>>(x);                  // + zero BN accumulators
    conv_kernel<<<dim3(1024, 2), 256, smem_bytes>>>(w, bias, out);
    params_kernel<<<1, 64>>>(gamma, beta);
    finalize_kernel<<<1024, 256>>>(out);                 // in-place BN + ReLU
}